// round 1
// baseline (speedup 1.0000x reference)
#include <cuda_runtime.h>
#include <cstdint>

// ---------------- problem constants ----------------
#define NNODES 50000
#define NEDGES 400000
#define ETOT   (NEDGES + NNODES)   // self-loops appended
#define NEG_SLOPE 0.2f
#define EPS 1e-5f

// ---------------- scratch (device globals; no allocs allowed) ----------------
__device__ float g_h  [NNODES * 256];   // post-GEMM hidden
__device__ float g_acc[NNODES * 256];   // edge-aggregation accumulator
__device__ float g_x  [NNODES * 256];   // activation between layers
__device__ float g_esrc[NNODES * 4];
__device__ float g_edst[NNODES * 4];
__device__ float g_denom[NNODES * 4];
__device__ float g_stats[1024];         // [sum(256) | sumsq(256) | scale(256) | shift(256)]

// ---------------- GEMM: C[n,m] = sum_k X[n,k] * W[m,k] (NT, both K-major) ----
// BM=64, BN=64, BK=32, 256 threads, 4x4 microtile.
__global__ void gemm_nt(const float* __restrict__ X, const float* __restrict__ W,
                        float* __restrict__ C, int Nrows, int K, int M)
{
    __shared__ float Xs[64][33];
    __shared__ float Ws[64][33];

    const int tid = threadIdx.x;
    const int bx = blockIdx.x;      // col tile (M/64)
    const int by = blockIdx.y;      // row tile
    const int tx = tid & 15;
    const int ty = tid >> 4;

    const int row_base = by * 64;
    const int col_base = bx * 64;

    float acc[4][4];
#pragma unroll
    for (int i = 0; i < 4; i++)
#pragma unroll
        for (int j = 0; j < 4; j++) acc[i][j] = 0.f;

    for (int k0 = 0; k0 < K; k0 += 32) {
        // load X tile: 64 rows x 32 k  (512 float4, 2 per thread)
#pragma unroll
        for (int l = 0; l < 2; l++) {
            int i = tid + l * 256;
            int r = i >> 3;
            int kk = (i & 7) * 4;
            int gr = row_base + r;
            float4 v = make_float4(0.f, 0.f, 0.f, 0.f);
            if (gr < Nrows)
                v = *reinterpret_cast<const float4*>(X + (size_t)gr * K + k0 + kk);
            Xs[r][kk + 0] = v.x; Xs[r][kk + 1] = v.y;
            Xs[r][kk + 2] = v.z; Xs[r][kk + 3] = v.w;
        }
        // load W tile: 64 rows (cols of C) x 32 k
#pragma unroll
        for (int l = 0; l < 2; l++) {
            int i = tid + l * 256;
            int r = i >> 3;
            int kk = (i & 7) * 4;
            float4 v = *reinterpret_cast<const float4*>(W + (size_t)(col_base + r) * K + k0 + kk);
            Ws[r][kk + 0] = v.x; Ws[r][kk + 1] = v.y;
            Ws[r][kk + 2] = v.z; Ws[r][kk + 3] = v.w;
        }
        __syncthreads();

#pragma unroll 8
        for (int kk = 0; kk < 32; kk++) {
            float a[4], b[4];
#pragma unroll
            for (int i = 0; i < 4; i++) a[i] = Xs[ty * 4 + i][kk];
#pragma unroll
            for (int j = 0; j < 4; j++) b[j] = Ws[tx * 4 + j][kk];
#pragma unroll
            for (int i = 0; i < 4; i++)
#pragma unroll
                for (int j = 0; j < 4; j++) acc[i][j] += a[i] * b[j];
        }
        __syncthreads();
    }

#pragma unroll
    for (int i = 0; i < 4; i++) {
        int gr = row_base + ty * 4 + i;
        if (gr < Nrows) {
            float4 v = make_float4(acc[i][0], acc[i][1], acc[i][2], acc[i][3]);
            *reinterpret_cast<float4*>(C + (size_t)gr * M + col_base + tx * 4) = v;
        }
    }
}

// ---------------- attention scores: e_src[n,h] = dot(h[n,h,:], a_src[h,:]) ----
template <int H, int C>
__global__ void attn_scores(const float* __restrict__ h,
                            const float* __restrict__ a_src,
                            const float* __restrict__ a_dst,
                            float* __restrict__ esrc, float* __restrict__ edst)
{
    const int D = H * C;
    __shared__ float s_as[D], s_ad[D];
    for (int i = threadIdx.x; i < D; i += blockDim.x) { s_as[i] = a_src[i]; s_ad[i] = a_dst[i]; }
    __syncthreads();

    int n = blockIdx.x * (blockDim.x / 32) + (threadIdx.x >> 5);
    if (n >= NNODES) return;
    int lane = threadIdx.x & 31;

    const int PER = D / 32;
    int c0 = lane * PER;
    float ss = 0.f, sd = 0.f;
#pragma unroll
    for (int i = 0; i < PER; i++) {
        float v = h[(size_t)n * D + c0 + i];
        ss += v * s_as[c0 + i];
        sd += v * s_ad[c0 + i];
    }
    const int G = 32 / H;  // lanes per head
#pragma unroll
    for (int off = G / 2; off > 0; off >>= 1) {
        ss += __shfl_xor_sync(0xffffffffu, ss, off);
        sd += __shfl_xor_sync(0xffffffffu, sd, off);
    }
    if ((lane & (G - 1)) == 0) {
        int hh = lane / G;
        esrc[n * H + hh] = ss;
        edst[n * H + hh] = sd;
    }
}

// ---------------- edge pass: acc[dst] += w*h[src], denom[dst] += w ----------
template <int H, int C>
__global__ void edge_kernel(const int* __restrict__ src, const int* __restrict__ dst,
                            const float* __restrict__ h,
                            const float* __restrict__ esrc, const float* __restrict__ edst,
                            float* __restrict__ acc, float* __restrict__ denom)
{
    int e = blockIdx.x * (blockDim.x / 32) + (threadIdx.x >> 5);
    if (e >= ETOT) return;
    int lane = threadIdx.x & 31;

    int s, d;
    if (e < NEDGES) { s = src[e]; d = dst[e]; }
    else            { s = d = e - NEDGES; }

    const int D = H * C;
    float wl = 0.f;
    if (lane < H) {
        float v = esrc[s * H + lane] + edst[d * H + lane];
        v = (v > 0.f) ? v : NEG_SLOPE * v;
        wl = __expf(v);
        atomicAdd(&denom[d * H + lane], wl);
    }
    float wh[H];
#pragma unroll
    for (int hh = 0; hh < H; hh++) wh[hh] = __shfl_sync(0xffffffffu, wl, hh);

    const int PER = D / 32;   // 8 (H=4) or 4 (H=1)
    int c0 = lane * PER;
    const float* hp = h + (size_t)s * D + c0;
    float* ap = acc + (size_t)d * D + c0;
#pragma unroll
    for (int i = 0; i < PER; i += 4) {
        float4 v = *reinterpret_cast<const float4*>(hp + i);
        float wf = wh[(c0 + i) / C];
        atomicAdd(ap + i + 0, v.x * wf);
        atomicAdd(ap + i + 1, v.y * wf);
        atomicAdd(ap + i + 2, v.z * wf);
        atomicAdd(ap + i + 3, v.w * wf);
    }
}

// ---------------- finalize (layers 0/1): x = acc/denom + b; fused stats -----
__global__ void finalize_stats(const float* __restrict__ acc, const float* __restrict__ denom,
                               const float* __restrict__ b, float* __restrict__ xout,
                               float* __restrict__ gsum, float* __restrict__ gsumsq)
{
    int c = threadIdx.x;               // 256 channels
    int n0 = blockIdx.x * 64;
    int n1 = min(n0 + 64, NNODES);
    float bc = b[c];
    float s = 0.f, s2 = 0.f;
    for (int n = n0; n < n1; n++) {
        float v = acc[(size_t)n * 256 + c] / denom[n * 4 + (c >> 6)] + bc;
        xout[(size_t)n * 256 + c] = v;
        s += v;
        s2 += v * v;
    }
    atomicAdd(&gsum[c], s);
    atomicAdd(&gsumsq[c], s2);
}

// ---------------- norm prep: per-channel scale/shift from sum/sumsq ---------
__global__ void norm_prep(const float* __restrict__ gsum, const float* __restrict__ gsumsq,
                          const float* __restrict__ gw, const float* __restrict__ gb,
                          const float* __restrict__ ms,
                          float* __restrict__ scale, float* __restrict__ shift)
{
    int c = threadIdx.x;
    const float invN = 1.f / (float)NNODES;
    float mean = gsum[c] * invN;
    float msq = gsumsq[c] * invN;
    float mm = mean * ms[c];
    float var = msq - 2.f * mm * mean + mm * mm;
    float sc = gw[c] * rsqrtf(var + EPS);
    scale[c] = sc;
    shift[c] = gb[c] - sc * mm;
}

// ---------------- norm apply + relu (in place) ------------------------------
__global__ void norm_apply(float* __restrict__ x, const float* __restrict__ scale,
                           const float* __restrict__ shift)
{
    size_t total = (size_t)NNODES * 256;
    for (size_t i = (size_t)blockIdx.x * blockDim.x + threadIdx.x; i < total;
         i += (size_t)gridDim.x * blockDim.x) {
        int c = (int)(i & 255);
        float v = scale[c] * x[i] + shift[c];
        x[i] = v > 0.f ? v : 0.f;
    }
}

// ---------------- finalize layer2 + output linear ---------------------------
__global__ void finalize_out(const float* __restrict__ acc, const float* __restrict__ denom,
                             const float* __restrict__ b2, const float* __restrict__ ow,
                             const float* __restrict__ ob, float* __restrict__ out)
{
    int n = blockIdx.x * (blockDim.x / 32) + (threadIdx.x >> 5);
    if (n >= NNODES) return;
    int lane = threadIdx.x & 31;
    float inv = 1.f / denom[n * 4];       // H=1 stored at stride 4? no: stride 1 region, see launch
    // NOTE: layer-2 denom is stored densely at g_denom[n] (H=1)
    inv = 1.f / denom[n];
    float d0 = 0.f, d1 = 0.f;
#pragma unroll
    for (int i = 0; i < 4; i++) {
        int c = lane * 4 + i;
        float v = acc[(size_t)n * 128 + c] * inv + b2[c];
        d0 += v * ow[c];
        d1 += v * ow[128 + c];
    }
#pragma unroll
    for (int off = 16; off > 0; off >>= 1) {
        d0 += __shfl_xor_sync(0xffffffffu, d0, off);
        d1 += __shfl_xor_sync(0xffffffffu, d1, off);
    }
    if (lane == 0) {
        out[n * 2 + 0] = d0 + ob[0];
        out[n * 2 + 1] = d1 + ob[1];
    }
}

// ---------------- launch ----------------------------------------------------
extern "C" void kernel_launch(void* const* d_in, const int* in_sizes, int n_in,
                              void* d_out, int out_size)
{
    const float* x      = (const float*)d_in[0];
    const int*   ei     = (const int*)d_in[1];
    const float* W0     = (const float*)d_in[2];
    const float* a_src0 = (const float*)d_in[3];
    const float* a_dst0 = (const float*)d_in[4];
    const float* b0     = (const float*)d_in[5];
    const float* gnw0   = (const float*)d_in[6];
    const float* gnb0   = (const float*)d_in[7];
    const float* gnms0  = (const float*)d_in[8];
    const float* W1     = (const float*)d_in[9];
    const float* a_src1 = (const float*)d_in[10];
    const float* a_dst1 = (const float*)d_in[11];
    const float* b1     = (const float*)d_in[12];
    const float* gnw1   = (const float*)d_in[13];
    const float* gnb1   = (const float*)d_in[14];
    const float* gnms1  = (const float*)d_in[15];
    const float* W2     = (const float*)d_in[16];
    const float* a_src2 = (const float*)d_in[17];
    const float* a_dst2 = (const float*)d_in[18];
    const float* b2     = (const float*)d_in[19];
    const float* ow     = (const float*)d_in[20];
    const float* ob     = (const float*)d_in[21];

    const int* srcp = ei;
    const int* dstp = ei + NEDGES;
    float* out = (float*)d_out;

    float *ph, *pacc, *px, *pes, *ped, *pden, *pstats;
    cudaGetSymbolAddress((void**)&ph, g_h);
    cudaGetSymbolAddress((void**)&pacc, g_acc);
    cudaGetSymbolAddress((void**)&px, g_x);
    cudaGetSymbolAddress((void**)&pes, g_esrc);
    cudaGetSymbolAddress((void**)&ped, g_edst);
    cudaGetSymbolAddress((void**)&pden, g_denom);
    cudaGetSymbolAddress((void**)&pstats, g_stats);
    float* gsum = pstats;
    float* gsumsq = pstats + 256;
    float* scale = pstats + 512;
    float* shift = pstats + 768;

    const int NODE_WARP_BLOCKS = (NNODES + 7) / 8;   // warp per node, 8/block
    const int EDGE_BLOCKS = (ETOT + 7) / 8;          // warp per edge, 8/block
    const int FIN_BLOCKS = (NNODES + 63) / 64;
    dim3 gemm_grid0(4, FIN_BLOCKS);                  // M=256
    dim3 gemm_grid2(2, FIN_BLOCKS);                  // M=128

    // ---------- layer 0: 128 -> 256 (4 heads x 64) ----------
    gemm_nt<<<gemm_grid0, 256>>>(x, W0, ph, NNODES, 128, 256);
    attn_scores<4, 64><<<NODE_WARP_BLOCKS, 256>>>(ph, a_src0, a_dst0, pes, ped);
    cudaMemsetAsync(pacc, 0, (size_t)NNODES * 256 * sizeof(float));
    cudaMemsetAsync(pden, 0, (size_t)NNODES * 4 * sizeof(float));
    cudaMemsetAsync(pstats, 0, 512 * sizeof(float));
    edge_kernel<4, 64><<<EDGE_BLOCKS, 256>>>(srcp, dstp, ph, pes, ped, pacc, pden);
    finalize_stats<<<FIN_BLOCKS, 256>>>(pacc, pden, b0, px, gsum, gsumsq);
    norm_prep<<<1, 256>>>(gsum, gsumsq, gnw0, gnb0, gnms0, scale, shift);
    norm_apply<<<1024, 256>>>(px, scale, shift);

    // ---------- layer 1: 256 -> 256 (4 heads x 64) ----------
    gemm_nt<<<gemm_grid0, 256>>>(px, W1, ph, NNODES, 256, 256);
    attn_scores<4, 64><<<NODE_WARP_BLOCKS, 256>>>(ph, a_src1, a_dst1, pes, ped);
    cudaMemsetAsync(pacc, 0, (size_t)NNODES * 256 * sizeof(float));
    cudaMemsetAsync(pden, 0, (size_t)NNODES * 4 * sizeof(float));
    cudaMemsetAsync(pstats, 0, 512 * sizeof(float));
    edge_kernel<4, 64><<<EDGE_BLOCKS, 256>>>(srcp, dstp, ph, pes, ped, pacc, pden);
    finalize_stats<<<FIN_BLOCKS, 256>>>(pacc, pden, b1, px, gsum, gsumsq);
    norm_prep<<<1, 256>>>(gsum, gsumsq, gnw1, gnb1, gnms1, scale, shift);
    norm_apply<<<1024, 256>>>(px, scale, shift);

    // ---------- layer 2: 256 -> 128 (1 head) + output linear ----------
    gemm_nt<<<gemm_grid2, 256>>>(px, W2, ph, NNODES, 256, 128);
    attn_scores<1, 128><<<NODE_WARP_BLOCKS, 256>>>(ph, a_src2, a_dst2, pes, ped);
    cudaMemsetAsync(pacc, 0, (size_t)NNODES * 128 * sizeof(float));
    cudaMemsetAsync(pden, 0, (size_t)NNODES * sizeof(float));
    edge_kernel<1, 128><<<EDGE_BLOCKS, 256>>>(srcp, dstp, ph, pes, ped, pacc, pden);
    finalize_out<<<NODE_WARP_BLOCKS, 256>>>(pacc, pden, b2, ow, ob, out);
}

// round 2
// speedup vs baseline: 2.9078x; 2.9078x over previous
#include <cuda_runtime.h>
#include <cstdint>

// ---------------- problem constants ----------------
#define NNODES 50000
#define NEDGES 400000
#define ETOT   (NEDGES + NNODES)   // self-loops appended
#define NEG_SLOPE 0.2f
#define EPS 1e-5f

// ---------------- scratch (device globals; no allocs allowed) ----------------
__device__ float g_h  [NNODES * 256];   // post-GEMM hidden
__device__ float g_acc[NNODES * 256];   // edge-aggregation accumulator
__device__ float g_x  [NNODES * 256];   // activation between layers
__device__ float g_esrc[NNODES * 4];
__device__ float g_edst[NNODES * 4];
__device__ float g_denom[NNODES * 4];
__device__ float g_stats[1024];         // [sum(256) | sumsq(256) | scale(256) | shift(256)]

// ---------------- helpers ----------------------------------------------------
__device__ __forceinline__ uint32_t f2tf32(float x) {
    uint32_t u;
    asm("cvt.rna.tf32.f32 %0, %1;" : "=r"(u) : "f"(x));
    return u;
}

__device__ __forceinline__ void mma_tf32(float& c0, float& c1, float& c2, float& c3,
                                         uint32_t a0, uint32_t a1, uint32_t a2, uint32_t a3,
                                         uint32_t b0, uint32_t b1) {
    asm volatile(
        "mma.sync.aligned.m16n8k8.row.col.f32.tf32.tf32.f32 "
        "{%0,%1,%2,%3}, {%4,%5,%6,%7}, {%8,%9}, {%0,%1,%2,%3};"
        : "+f"(c0), "+f"(c1), "+f"(c2), "+f"(c3)
        : "r"(a0), "r"(a1), "r"(a2), "r"(a3), "r"(b0), "r"(b1));
}

// ---------------- tf32 tensor-core GEMM: C[n,m] = sum_k X[n,k]*W[m,k] -------
// BM=128, BN=128, BK=32, 256 threads (8 warps, 4x2), warp tile 32x64.
__global__ void gemm_tf32(const float* __restrict__ X, const float* __restrict__ W,
                          float* __restrict__ C, int Nrows, int K, int M)
{
    __shared__ float As[128][36];   // [row][k], pad 4
    __shared__ float Bs[128][36];   // [col(m)][k], pad 4

    const int tid = threadIdx.x;
    const int rowBase = blockIdx.y * 128;
    const int colBase = blockIdx.x * 128;
    const int warp = tid >> 5;
    const int lane = tid & 31;
    const int wr = (warp & 3) * 32;   // warp row offset in tile
    const int wc = (warp >> 2) * 64;  // warp col offset in tile
    const int grp = lane >> 2;        // 0..7
    const int tig = lane & 3;         // 0..3

    float c[2][8][4];
#pragma unroll
    for (int t = 0; t < 2; t++)
#pragma unroll
        for (int u = 0; u < 8; u++)
#pragma unroll
            for (int v = 0; v < 4; v++) c[t][u][v] = 0.f;

    for (int k0 = 0; k0 < K; k0 += 32) {
        // load A tile: 128 rows x 32 k = 1024 float4
#pragma unroll
        for (int l = 0; l < 4; l++) {
            int idx = tid + l * 256;
            int r = idx >> 3;
            int kk = (idx & 7) * 4;
            int gr = rowBase + r;
            float4 v = make_float4(0.f, 0.f, 0.f, 0.f);
            if (gr < Nrows)
                v = *reinterpret_cast<const float4*>(X + (size_t)gr * K + k0 + kk);
            As[r][kk + 0] = __uint_as_float(f2tf32(v.x));
            As[r][kk + 1] = __uint_as_float(f2tf32(v.y));
            As[r][kk + 2] = __uint_as_float(f2tf32(v.z));
            As[r][kk + 3] = __uint_as_float(f2tf32(v.w));
        }
        // load B tile: 128 cols(m) x 32 k
#pragma unroll
        for (int l = 0; l < 4; l++) {
            int idx = tid + l * 256;
            int r = idx >> 3;
            int kk = (idx & 7) * 4;
            float4 v = *reinterpret_cast<const float4*>(W + (size_t)(colBase + r) * K + k0 + kk);
            Bs[r][kk + 0] = __uint_as_float(f2tf32(v.x));
            Bs[r][kk + 1] = __uint_as_float(f2tf32(v.y));
            Bs[r][kk + 2] = __uint_as_float(f2tf32(v.z));
            Bs[r][kk + 3] = __uint_as_float(f2tf32(v.w));
        }
        __syncthreads();

#pragma unroll
        for (int kk = 0; kk < 32; kk += 8) {
            uint32_t a[2][4];
#pragma unroll
            for (int t = 0; t < 2; t++) {
                int r0 = wr + t * 16 + grp;
                a[t][0] = __float_as_uint(As[r0][kk + tig]);
                a[t][1] = __float_as_uint(As[r0 + 8][kk + tig]);
                a[t][2] = __float_as_uint(As[r0][kk + tig + 4]);
                a[t][3] = __float_as_uint(As[r0 + 8][kk + tig + 4]);
            }
            uint32_t b[8][2];
#pragma unroll
            for (int u = 0; u < 8; u++) {
                int cB = wc + u * 8 + grp;
                b[u][0] = __float_as_uint(Bs[cB][kk + tig]);
                b[u][1] = __float_as_uint(Bs[cB][kk + tig + 4]);
            }
#pragma unroll
            for (int t = 0; t < 2; t++)
#pragma unroll
                for (int u = 0; u < 8; u++)
                    mma_tf32(c[t][u][0], c[t][u][1], c[t][u][2], c[t][u][3],
                             a[t][0], a[t][1], a[t][2], a[t][3], b[u][0], b[u][1]);
        }
        __syncthreads();
    }

    // epilogue
#pragma unroll
    for (int t = 0; t < 2; t++) {
        int gr0 = rowBase + wr + t * 16 + grp;
        int gr1 = gr0 + 8;
#pragma unroll
        for (int u = 0; u < 8; u++) {
            int gc = colBase + wc + u * 8 + tig * 2;
            if (gr0 < Nrows)
                *reinterpret_cast<float2*>(C + (size_t)gr0 * M + gc) =
                    make_float2(c[t][u][0], c[t][u][1]);
            if (gr1 < Nrows)
                *reinterpret_cast<float2*>(C + (size_t)gr1 * M + gc) =
                    make_float2(c[t][u][2], c[t][u][3]);
        }
    }
}

// ---------------- attention scores: e_src[n,h] = dot(h[n,h,:], a_src[h,:]) ----
template <int H, int C>
__global__ void attn_scores(const float* __restrict__ h,
                            const float* __restrict__ a_src,
                            const float* __restrict__ a_dst,
                            float* __restrict__ esrc, float* __restrict__ edst)
{
    const int D = H * C;
    __shared__ float s_as[D], s_ad[D];
    for (int i = threadIdx.x; i < D; i += blockDim.x) { s_as[i] = a_src[i]; s_ad[i] = a_dst[i]; }
    __syncthreads();

    int n = blockIdx.x * (blockDim.x / 32) + (threadIdx.x >> 5);
    if (n >= NNODES) return;
    int lane = threadIdx.x & 31;

    const int PER = D / 32;
    int c0 = lane * PER;
    float ss = 0.f, sd = 0.f;
#pragma unroll
    for (int i = 0; i < PER; i++) {
        float v = h[(size_t)n * D + c0 + i];
        ss += v * s_as[c0 + i];
        sd += v * s_ad[c0 + i];
    }
    const int G = 32 / H;  // lanes per head
#pragma unroll
    for (int off = G / 2; off > 0; off >>= 1) {
        ss += __shfl_xor_sync(0xffffffffu, ss, off);
        sd += __shfl_xor_sync(0xffffffffu, sd, off);
    }
    if ((lane & (G - 1)) == 0) {
        int hh = lane / G;
        esrc[n * H + hh] = ss;
        edst[n * H + hh] = sd;
    }
}

// ---------------- edge pass: acc[dst] += w*h[src], denom[dst] += w ----------
template <int H, int C>
__global__ void edge_kernel(const int* __restrict__ src, const int* __restrict__ dst,
                            const float* __restrict__ h,
                            const float* __restrict__ esrc, const float* __restrict__ edst,
                            float* __restrict__ acc, float* __restrict__ denom)
{
    int e = blockIdx.x * (blockDim.x / 32) + (threadIdx.x >> 5);
    if (e >= ETOT) return;
    int lane = threadIdx.x & 31;

    int s, d;
    if (e < NEDGES) { s = src[e]; d = dst[e]; }
    else            { s = d = e - NEDGES; }

    const int D = H * C;
    float wl = 0.f;
    if (lane < H) {
        float v = esrc[s * H + lane] + edst[d * H + lane];
        v = (v > 0.f) ? v : NEG_SLOPE * v;
        wl = __expf(v);
        atomicAdd(&denom[d * H + lane], wl);
    }
    float wh[H];
#pragma unroll
    for (int hh = 0; hh < H; hh++) wh[hh] = __shfl_sync(0xffffffffu, wl, hh);

    const int PER = D / 32;   // 8 (H=4) or 4 (H=1)
    int c0 = lane * PER;
    const float* hp = h + (size_t)s * D + c0;
    float* ap = acc + (size_t)d * D + c0;
#pragma unroll
    for (int i = 0; i < PER; i += 4) {
        float4 v = *reinterpret_cast<const float4*>(hp + i);
        float wf = wh[(c0 + i) / C];
        asm volatile("red.global.add.v4.f32 [%0], {%1, %2, %3, %4};"
                     :: "l"(ap + i), "f"(v.x * wf), "f"(v.y * wf),
                        "f"(v.z * wf), "f"(v.w * wf)
                     : "memory");
    }
}

// ---------------- finalize (layers 0/1): x = acc/denom + b; fused stats -----
__global__ void finalize_stats(const float* __restrict__ acc, const float* __restrict__ denom,
                               const float* __restrict__ b, float* __restrict__ xout,
                               float* __restrict__ gsum, float* __restrict__ gsumsq)
{
    int c = threadIdx.x;               // 256 channels
    int n0 = blockIdx.x * 64;
    int n1 = min(n0 + 64, NNODES);
    float bc = b[c];
    float s = 0.f, s2 = 0.f;
#pragma unroll 4
    for (int n = n0; n < n1; n++) {
        float v = acc[(size_t)n * 256 + c] / denom[n * 4 + (c >> 6)] + bc;
        xout[(size_t)n * 256 + c] = v;
        s += v;
        s2 += v * v;
    }
    atomicAdd(&gsum[c], s);
    atomicAdd(&gsumsq[c], s2);
}

// ---------------- norm prep: per-channel scale/shift from sum/sumsq ---------
__global__ void norm_prep(const float* __restrict__ gsum, const float* __restrict__ gsumsq,
                          const float* __restrict__ gw, const float* __restrict__ gb,
                          const float* __restrict__ ms,
                          float* __restrict__ scale, float* __restrict__ shift)
{
    int c = threadIdx.x;
    const float invN = 1.f / (float)NNODES;
    float mean = gsum[c] * invN;
    float msq = gsumsq[c] * invN;
    float mm = mean * ms[c];
    float var = msq - 2.f * mm * mean + mm * mm;
    float sc = gw[c] * rsqrtf(var + EPS);
    scale[c] = sc;
    shift[c] = gb[c] - sc * mm;
}

// ---------------- norm apply + relu (in place) ------------------------------
__global__ void norm_apply(float* __restrict__ x, const float* __restrict__ scale,
                           const float* __restrict__ shift)
{
    size_t total = (size_t)NNODES * 256;
    for (size_t i = (size_t)blockIdx.x * blockDim.x + threadIdx.x; i < total;
         i += (size_t)gridDim.x * blockDim.x) {
        int c = (int)(i & 255);
        float v = scale[c] * x[i] + shift[c];
        x[i] = v > 0.f ? v : 0.f;
    }
}

// ---------------- finalize layer2 + output linear ---------------------------
__global__ void finalize_out(const float* __restrict__ acc, const float* __restrict__ denom,
                             const float* __restrict__ b2, const float* __restrict__ ow,
                             const float* __restrict__ ob, float* __restrict__ out)
{
    int n = blockIdx.x * (blockDim.x / 32) + (threadIdx.x >> 5);
    if (n >= NNODES) return;
    int lane = threadIdx.x & 31;
    float inv = 1.f / denom[n];      // layer-2 denom stored densely (H=1)
    float d0 = 0.f, d1 = 0.f;
#pragma unroll
    for (int i = 0; i < 4; i++) {
        int c = lane * 4 + i;
        float v = acc[(size_t)n * 128 + c] * inv + b2[c];
        d0 += v * ow[c];
        d1 += v * ow[128 + c];
    }
#pragma unroll
    for (int off = 16; off > 0; off >>= 1) {
        d0 += __shfl_xor_sync(0xffffffffu, d0, off);
        d1 += __shfl_xor_sync(0xffffffffu, d1, off);
    }
    if (lane == 0) {
        out[n * 2 + 0] = d0 + ob[0];
        out[n * 2 + 1] = d1 + ob[1];
    }
}

// ---------------- launch ----------------------------------------------------
extern "C" void kernel_launch(void* const* d_in, const int* in_sizes, int n_in,
                              void* d_out, int out_size)
{
    const float* x      = (const float*)d_in[0];
    const int*   ei     = (const int*)d_in[1];
    const float* W0     = (const float*)d_in[2];
    const float* a_src0 = (const float*)d_in[3];
    const float* a_dst0 = (const float*)d_in[4];
    const float* b0     = (const float*)d_in[5];
    const float* gnw0   = (const float*)d_in[6];
    const float* gnb0   = (const float*)d_in[7];
    const float* gnms0  = (const float*)d_in[8];
    const float* W1     = (const float*)d_in[9];
    const float* a_src1 = (const float*)d_in[10];
    const float* a_dst1 = (const float*)d_in[11];
    const float* b1     = (const float*)d_in[12];
    const float* gnw1   = (const float*)d_in[13];
    const float* gnb1   = (const float*)d_in[14];
    const float* gnms1  = (const float*)d_in[15];
    const float* W2     = (const float*)d_in[16];
    const float* a_src2 = (const float*)d_in[17];
    const float* a_dst2 = (const float*)d_in[18];
    const float* b2     = (const float*)d_in[19];
    const float* ow     = (const float*)d_in[20];
    const float* ob     = (const float*)d_in[21];

    const int* srcp = ei;
    const int* dstp = ei + NEDGES;
    float* out = (float*)d_out;

    float *ph, *pacc, *px, *pes, *ped, *pden, *pstats;
    cudaGetSymbolAddress((void**)&ph, g_h);
    cudaGetSymbolAddress((void**)&pacc, g_acc);
    cudaGetSymbolAddress((void**)&px, g_x);
    cudaGetSymbolAddress((void**)&pes, g_esrc);
    cudaGetSymbolAddress((void**)&ped, g_edst);
    cudaGetSymbolAddress((void**)&pden, g_denom);
    cudaGetSymbolAddress((void**)&pstats, g_stats);
    float* gsum = pstats;
    float* gsumsq = pstats + 256;
    float* scale = pstats + 512;
    float* shift = pstats + 768;

    const int NODE_WARP_BLOCKS = (NNODES + 7) / 8;   // warp per node, 8/block
    const int EDGE_BLOCKS = (ETOT + 7) / 8;          // warp per edge, 8/block
    const int FIN_BLOCKS = (NNODES + 63) / 64;
    const int ROW_TILES = (NNODES + 127) / 128;      // 391
    dim3 gemm_grid0(2, ROW_TILES);                   // M=256
    dim3 gemm_grid2(1, ROW_TILES);                   // M=128

    // ---------- layer 0: 128 -> 256 (4 heads x 64) ----------
    gemm_tf32<<<gemm_grid0, 256>>>(x, W0, ph, NNODES, 128, 256);
    attn_scores<4, 64><<<NODE_WARP_BLOCKS, 256>>>(ph, a_src0, a_dst0, pes, ped);
    cudaMemsetAsync(pacc, 0, (size_t)NNODES * 256 * sizeof(float));
    cudaMemsetAsync(pden, 0, (size_t)NNODES * 4 * sizeof(float));
    cudaMemsetAsync(pstats, 0, 512 * sizeof(float));
    edge_kernel<4, 64><<<EDGE_BLOCKS, 256>>>(srcp, dstp, ph, pes, ped, pacc, pden);
    finalize_stats<<<FIN_BLOCKS, 256>>>(pacc, pden, b0, px, gsum, gsumsq);
    norm_prep<<<1, 256>>>(gsum, gsumsq, gnw0, gnb0, gnms0, scale, shift);
    norm_apply<<<1024, 256>>>(px, scale, shift);

    // ---------- layer 1: 256 -> 256 (4 heads x 64) ----------
    gemm_tf32<<<gemm_grid0, 256>>>(px, W1, ph, NNODES, 256, 256);
    attn_scores<4, 64><<<NODE_WARP_BLOCKS, 256>>>(ph, a_src1, a_dst1, pes, ped);
    cudaMemsetAsync(pacc, 0, (size_t)NNODES * 256 * sizeof(float));
    cudaMemsetAsync(pden, 0, (size_t)NNODES * 4 * sizeof(float));
    cudaMemsetAsync(pstats, 0, 512 * sizeof(float));
    edge_kernel<4, 64><<<EDGE_BLOCKS, 256>>>(srcp, dstp, ph, pes, ped, pacc, pden);
    finalize_stats<<<FIN_BLOCKS, 256>>>(pacc, pden, b1, px, gsum, gsumsq);
    norm_prep<<<1, 256>>>(gsum, gsumsq, gnw1, gnb1, gnms1, scale, shift);
    norm_apply<<<1024, 256>>>(px, scale, shift);

    // ---------- layer 2: 256 -> 128 (1 head) + output linear ----------
    gemm_tf32<<<gemm_grid2, 256>>>(px, W2, ph, NNODES, 256, 128);
    attn_scores<1, 128><<<NODE_WARP_BLOCKS, 256>>>(ph, a_src2, a_dst2, pes, ped);
    cudaMemsetAsync(pacc, 0, (size_t)NNODES * 128 * sizeof(float));
    cudaMemsetAsync(pden, 0, (size_t)NNODES * sizeof(float));
    edge_kernel<1, 128><<<EDGE_BLOCKS, 256>>>(srcp, dstp, ph, pes, ped, pacc, pden);
    finalize_out<<<NODE_WARP_BLOCKS, 256>>>(pacc, pden, b2, ow, ob, out);
}

// round 3
// speedup vs baseline: 3.7470x; 1.2886x over previous
#include <cuda_runtime.h>
#include <cstdint>

// ---------------- problem constants ----------------
#define NNODES 50000
#define NEDGES 400000
#define NEG_SLOPE 0.2f
#define EPS 1e-5f

// ---------------- scratch (device globals; no allocs allowed) ----------------
__device__ float g_h  [NNODES * 256];   // post-GEMM hidden
__device__ float g_x  [NNODES * 256];   // activation between layers
__device__ float g_esrc[NNODES * 4];
__device__ float g_edst[NNODES * 4];
__device__ float g_stats[1024];         // [sum(256) | sumsq(256) | scale(256) | shift(256)]
__device__ int   g_deg[NNODES];
__device__ int   g_off[NNODES + 1];
__device__ int   g_pos[NNODES];
__device__ int   g_csr[NEDGES];         // src ids grouped by dst

// ---------------- helpers ----------------------------------------------------
__device__ __forceinline__ uint32_t f2tf32(float x) {
    uint32_t u;
    asm("cvt.rna.tf32.f32 %0, %1;" : "=r"(u) : "f"(x));
    return u;
}

__device__ __forceinline__ void mma_tf32(float& c0, float& c1, float& c2, float& c3,
                                         uint32_t a0, uint32_t a1, uint32_t a2, uint32_t a3,
                                         uint32_t b0, uint32_t b1) {
    asm volatile(
        "mma.sync.aligned.m16n8k8.row.col.f32.tf32.tf32.f32 "
        "{%0,%1,%2,%3}, {%4,%5,%6,%7}, {%8,%9}, {%0,%1,%2,%3};"
        : "+f"(c0), "+f"(c1), "+f"(c2), "+f"(c3)
        : "r"(a0), "r"(a1), "r"(a2), "r"(a3), "r"(b0), "r"(b1));
}

// ---------------- CSR build --------------------------------------------------
__global__ void csr_count(const int* __restrict__ dst, int* __restrict__ deg)
{
    int e = blockIdx.x * blockDim.x + threadIdx.x;
    if (e < NEDGES) atomicAdd(&deg[dst[e]], 1);
}

__global__ void csr_scan(const int* __restrict__ deg, int* __restrict__ off,
                         int* __restrict__ pos)
{
    const int CHUNK = (NNODES + 1023) / 1024;   // 49
    __shared__ int ss[1024];
    int t = threadIdx.x;
    int base = t * CHUNK;
    int s = 0;
    for (int k = 0; k < CHUNK; k++) {
        int i = base + k;
        if (i < NNODES) s += deg[i];
    }
    ss[t] = s;
    __syncthreads();
    for (int o = 1; o < 1024; o <<= 1) {
        int v = (t >= o) ? ss[t - o] : 0;
        __syncthreads();
        ss[t] += v;
        __syncthreads();
    }
    int run = (t > 0) ? ss[t - 1] : 0;
    for (int k = 0; k < CHUNK; k++) {
        int i = base + k;
        if (i < NNODES) {
            off[i] = run;
            pos[i] = run;
            run += deg[i];
        }
    }
    if (t == 1023) off[NNODES] = ss[1023];
}

__global__ void csr_fill(const int* __restrict__ src, const int* __restrict__ dst,
                         int* __restrict__ pos, int* __restrict__ csr)
{
    int e = blockIdx.x * blockDim.x + threadIdx.x;
    if (e < NEDGES) {
        int p = atomicAdd(&pos[dst[e]], 1);
        csr[p] = src[e];
    }
}

// ---------------- tf32 tensor-core GEMM: C[n,m] = sum_k X[n,k]*W[m,k] -------
// BM=128, BN=128, BK=32, 256 threads (8 warps, 4x2), warp tile 32x64.
// NORM: apply per-channel scale/shift + relu to X on load (fused GraphNorm).
template <int NORM>
__global__ void gemm_tf32(const float* __restrict__ X, const float* __restrict__ W,
                          float* __restrict__ C, int Nrows, int K, int M,
                          const float* __restrict__ scale, const float* __restrict__ shift)
{
    __shared__ float As[128][36];
    __shared__ float Bs[128][36];

    const int tid = threadIdx.x;
    const int rowBase = blockIdx.y * 128;
    const int colBase = blockIdx.x * 128;
    const int warp = tid >> 5;
    const int lane = tid & 31;
    const int wr = (warp & 3) * 32;
    const int wc = (warp >> 2) * 64;
    const int grp = lane >> 2;
    const int tig = lane & 3;

    float c[2][8][4];
#pragma unroll
    for (int t = 0; t < 2; t++)
#pragma unroll
        for (int u = 0; u < 8; u++)
#pragma unroll
            for (int v = 0; v < 4; v++) c[t][u][v] = 0.f;

    for (int k0 = 0; k0 < K; k0 += 32) {
#pragma unroll
        for (int l = 0; l < 4; l++) {
            int idx = tid + l * 256;
            int r = idx >> 3;
            int kk = (idx & 7) * 4;
            int gr = rowBase + r;
            float4 v = make_float4(0.f, 0.f, 0.f, 0.f);
            if (gr < Nrows)
                v = *reinterpret_cast<const float4*>(X + (size_t)gr * K + k0 + kk);
            if (NORM) {
                float4 sc = *reinterpret_cast<const float4*>(scale + k0 + kk);
                float4 sh = *reinterpret_cast<const float4*>(shift + k0 + kk);
                v.x = fmaxf(fmaf(sc.x, v.x, sh.x), 0.f);
                v.y = fmaxf(fmaf(sc.y, v.y, sh.y), 0.f);
                v.z = fmaxf(fmaf(sc.z, v.z, sh.z), 0.f);
                v.w = fmaxf(fmaf(sc.w, v.w, sh.w), 0.f);
            }
            As[r][kk + 0] = __uint_as_float(f2tf32(v.x));
            As[r][kk + 1] = __uint_as_float(f2tf32(v.y));
            As[r][kk + 2] = __uint_as_float(f2tf32(v.z));
            As[r][kk + 3] = __uint_as_float(f2tf32(v.w));
        }
#pragma unroll
        for (int l = 0; l < 4; l++) {
            int idx = tid + l * 256;
            int r = idx >> 3;
            int kk = (idx & 7) * 4;
            float4 v = *reinterpret_cast<const float4*>(W + (size_t)(colBase + r) * K + k0 + kk);
            Bs[r][kk + 0] = __uint_as_float(f2tf32(v.x));
            Bs[r][kk + 1] = __uint_as_float(f2tf32(v.y));
            Bs[r][kk + 2] = __uint_as_float(f2tf32(v.z));
            Bs[r][kk + 3] = __uint_as_float(f2tf32(v.w));
        }
        __syncthreads();

#pragma unroll
        for (int kk = 0; kk < 32; kk += 8) {
            uint32_t a[2][4];
#pragma unroll
            for (int t = 0; t < 2; t++) {
                int r0 = wr + t * 16 + grp;
                a[t][0] = __float_as_uint(As[r0][kk + tig]);
                a[t][1] = __float_as_uint(As[r0 + 8][kk + tig]);
                a[t][2] = __float_as_uint(As[r0][kk + tig + 4]);
                a[t][3] = __float_as_uint(As[r0 + 8][kk + tig + 4]);
            }
            uint32_t b[8][2];
#pragma unroll
            for (int u = 0; u < 8; u++) {
                int cB = wc + u * 8 + grp;
                b[u][0] = __float_as_uint(Bs[cB][kk + tig]);
                b[u][1] = __float_as_uint(Bs[cB][kk + tig + 4]);
            }
#pragma unroll
            for (int t = 0; t < 2; t++)
#pragma unroll
                for (int u = 0; u < 8; u++)
                    mma_tf32(c[t][u][0], c[t][u][1], c[t][u][2], c[t][u][3],
                             a[t][0], a[t][1], a[t][2], a[t][3], b[u][0], b[u][1]);
        }
        __syncthreads();
    }

#pragma unroll
    for (int t = 0; t < 2; t++) {
        int gr0 = rowBase + wr + t * 16 + grp;
        int gr1 = gr0 + 8;
#pragma unroll
        for (int u = 0; u < 8; u++) {
            int gc = colBase + wc + u * 8 + tig * 2;
            if (gr0 < Nrows)
                *reinterpret_cast<float2*>(C + (size_t)gr0 * M + gc) =
                    make_float2(c[t][u][0], c[t][u][1]);
            if (gr1 < Nrows)
                *reinterpret_cast<float2*>(C + (size_t)gr1 * M + gc) =
                    make_float2(c[t][u][2], c[t][u][3]);
        }
    }
}

// ---------------- attention scores ------------------------------------------
template <int H, int C>
__global__ void attn_scores(const float* __restrict__ h,
                            const float* __restrict__ a_src,
                            const float* __restrict__ a_dst,
                            float* __restrict__ esrc, float* __restrict__ edst)
{
    const int D = H * C;
    __shared__ float s_as[D], s_ad[D];
    for (int i = threadIdx.x; i < D; i += blockDim.x) { s_as[i] = a_src[i]; s_ad[i] = a_dst[i]; }
    __syncthreads();

    int n = blockIdx.x * (blockDim.x / 32) + (threadIdx.x >> 5);
    if (n >= NNODES) return;
    int lane = threadIdx.x & 31;

    const int PER = D / 32;
    int c0 = lane * PER;
    float ss = 0.f, sd = 0.f;
#pragma unroll
    for (int i = 0; i < PER; i++) {
        float v = h[(size_t)n * D + c0 + i];
        ss += v * s_as[c0 + i];
        sd += v * s_ad[c0 + i];
    }
    const int G = 32 / H;
#pragma unroll
    for (int off = G / 2; off > 0; off >>= 1) {
        ss += __shfl_xor_sync(0xffffffffu, ss, off);
        sd += __shfl_xor_sync(0xffffffffu, sd, off);
    }
    if ((lane & (G - 1)) == 0) {
        int hh = lane / G;
        esrc[n * H + hh] = ss;
        edst[n * H + hh] = sd;
    }
}

// ---------------- pull aggregation + softmax-div + bias + fused stats -------
// Warp per destination node. H=4, C=64 (layers 0/1). 8 warps/block = 8 nodes.
__global__ void pull_stats(const int* __restrict__ off, const int* __restrict__ csr,
                           const float* __restrict__ h,
                           const float* __restrict__ esrc, const float* __restrict__ edst,
                           const float* __restrict__ bias, float* __restrict__ xout,
                           float* __restrict__ gsum, float* __restrict__ gsumsq)
{
    const int H = 4, D = 256, PER = 8;
    __shared__ float sm[PER * 256];     // [i][w][lane]

    int w = threadIdx.x >> 5;
    int lane = threadIdx.x & 31;
    int n = blockIdx.x * 8 + w;
    const int HH = lane >> 3;           // head owning this lane's channels

    float v[PER];
#pragma unroll
    for (int i = 0; i < PER; i++) v[i] = 0.f;

    if (n < NNODES) {
        int c0 = lane * PER;
        float ed_l = (lane < H) ? edst[n * H + lane] : 0.f;

        // self loop
        float wl = 0.f;
        if (lane < H) {
            float e = esrc[n * H + lane] + ed_l;
            e = (e > 0.f) ? e : NEG_SLOPE * e;
            wl = __expf(e);
        }
        float myw = __shfl_sync(0xffffffffu, wl, HH);
        float dn = myw;

        float acc[PER];
        {
            const float4* hp = reinterpret_cast<const float4*>(h + (size_t)n * D + c0);
            float4 p = hp[0], q = hp[1];
            acc[0] = myw * p.x; acc[1] = myw * p.y; acc[2] = myw * p.z; acc[3] = myw * p.w;
            acc[4] = myw * q.x; acc[5] = myw * q.y; acc[6] = myw * q.z; acc[7] = myw * q.w;
        }

        int jb = off[n], je = off[n + 1];
        for (int j = jb; j < je; j++) {
            int s = csr[j];
            float wl2 = 0.f;
            if (lane < H) {
                float e = esrc[s * H + lane] + ed_l;
                e = (e > 0.f) ? e : NEG_SLOPE * e;
                wl2 = __expf(e);
            }
            float w2 = __shfl_sync(0xffffffffu, wl2, HH);
            dn += w2;
            const float4* hp = reinterpret_cast<const float4*>(h + (size_t)s * D + c0);
            float4 p = hp[0], q = hp[1];
            acc[0] = fmaf(w2, p.x, acc[0]); acc[1] = fmaf(w2, p.y, acc[1]);
            acc[2] = fmaf(w2, p.z, acc[2]); acc[3] = fmaf(w2, p.w, acc[3]);
            acc[4] = fmaf(w2, q.x, acc[4]); acc[5] = fmaf(w2, q.y, acc[5]);
            acc[6] = fmaf(w2, q.z, acc[6]); acc[7] = fmaf(w2, q.w, acc[7]);
        }

        float inv = 1.f / (dn + 1e-16f);
#pragma unroll
        for (int i = 0; i < PER; i++) v[i] = fmaf(acc[i], inv, bias[c0 + i]);

        float4 o0 = make_float4(v[0], v[1], v[2], v[3]);
        float4 o1 = make_float4(v[4], v[5], v[6], v[7]);
        float4* xp = reinterpret_cast<float4*>(xout + (size_t)n * D + c0);
        xp[0] = o0; xp[1] = o1;
    }

    // fused per-block stats: sm[i*256 + w*32 + lane] conflict-free
#pragma unroll
    for (int i = 0; i < PER; i++) sm[i * 256 + w * 32 + lane] = v[i];
    __syncthreads();

    int c = threadIdx.x;                // channel
    int li = c >> 3, ii = c & 7;        // producing lane / i
    float s = 0.f, s2 = 0.f;
#pragma unroll
    for (int ww = 0; ww < 8; ww++) {
        float x = sm[ii * 256 + ww * 32 + li];
        s += x;
        s2 += x * x;
    }
    atomicAdd(&gsum[c], s);
    atomicAdd(&gsumsq[c], s2);
}

// ---------------- layer-2 pull + output linear ------------------------------
__global__ void pull_out(const int* __restrict__ off, const int* __restrict__ csr,
                         const float* __restrict__ h,
                         const float* __restrict__ esrc, const float* __restrict__ edst,
                         const float* __restrict__ b2, const float* __restrict__ ow,
                         const float* __restrict__ ob, float* __restrict__ out)
{
    const int D = 128, PER = 4;
    int w = threadIdx.x >> 5;
    int lane = threadIdx.x & 31;
    int n = blockIdx.x * 8 + w;
    if (n >= NNODES) return;
    int c0 = lane * PER;

    float ed_l = edst[n];
    float wl = 0.f;
    if (lane == 0) {
        float e = esrc[n] + ed_l;
        e = (e > 0.f) ? e : NEG_SLOPE * e;
        wl = __expf(e);
    }
    float myw = __shfl_sync(0xffffffffu, wl, 0);
    float dn = myw;

    float acc[PER];
    {
        float4 p = *reinterpret_cast<const float4*>(h + (size_t)n * D + c0);
        acc[0] = myw * p.x; acc[1] = myw * p.y; acc[2] = myw * p.z; acc[3] = myw * p.w;
    }

    int jb = off[n], je = off[n + 1];
    for (int j = jb; j < je; j++) {
        int s = csr[j];
        float wl2 = 0.f;
        if (lane == 0) {
            float e = esrc[s] + ed_l;
            e = (e > 0.f) ? e : NEG_SLOPE * e;
            wl2 = __expf(e);
        }
        float w2 = __shfl_sync(0xffffffffu, wl2, 0);
        dn += w2;
        float4 p = *reinterpret_cast<const float4*>(h + (size_t)s * D + c0);
        acc[0] = fmaf(w2, p.x, acc[0]); acc[1] = fmaf(w2, p.y, acc[1]);
        acc[2] = fmaf(w2, p.z, acc[2]); acc[3] = fmaf(w2, p.w, acc[3]);
    }

    float inv = 1.f / (dn + 1e-16f);
    float d0 = 0.f, d1 = 0.f;
#pragma unroll
    for (int i = 0; i < PER; i++) {
        float v = fmaf(acc[i], inv, b2[c0 + i]);
        d0 = fmaf(v, ow[c0 + i], d0);
        d1 = fmaf(v, ow[128 + c0 + i], d1);
    }
#pragma unroll
    for (int o = 16; o > 0; o >>= 1) {
        d0 += __shfl_xor_sync(0xffffffffu, d0, o);
        d1 += __shfl_xor_sync(0xffffffffu, d1, o);
    }
    if (lane == 0) {
        out[n * 2 + 0] = d0 + ob[0];
        out[n * 2 + 1] = d1 + ob[1];
    }
}

// ---------------- norm prep: per-channel scale/shift ------------------------
__global__ void norm_prep(const float* __restrict__ gsum, const float* __restrict__ gsumsq,
                          const float* __restrict__ gw, const float* __restrict__ gb,
                          const float* __restrict__ ms,
                          float* __restrict__ scale, float* __restrict__ shift)
{
    int c = threadIdx.x;
    const float invN = 1.f / (float)NNODES;
    float mean = gsum[c] * invN;
    float msq = gsumsq[c] * invN;
    float mm = mean * ms[c];
    float var = msq - 2.f * mm * mean + mm * mm;
    float sc = gw[c] * rsqrtf(var + EPS);
    scale[c] = sc;
    shift[c] = gb[c] - sc * mm;
}

// ---------------- launch ----------------------------------------------------
extern "C" void kernel_launch(void* const* d_in, const int* in_sizes, int n_in,
                              void* d_out, int out_size)
{
    const float* x      = (const float*)d_in[0];
    const int*   ei     = (const int*)d_in[1];
    const float* W0     = (const float*)d_in[2];
    const float* a_src0 = (const float*)d_in[3];
    const float* a_dst0 = (const float*)d_in[4];
    const float* b0     = (const float*)d_in[5];
    const float* gnw0   = (const float*)d_in[6];
    const float* gnb0   = (const float*)d_in[7];
    const float* gnms0  = (const float*)d_in[8];
    const float* W1     = (const float*)d_in[9];
    const float* a_src1 = (const float*)d_in[10];
    const float* a_dst1 = (const float*)d_in[11];
    const float* b1     = (const float*)d_in[12];
    const float* gnw1   = (const float*)d_in[13];
    const float* gnb1   = (const float*)d_in[14];
    const float* gnms1  = (const float*)d_in[15];
    const float* W2     = (const float*)d_in[16];
    const float* a_src2 = (const float*)d_in[17];
    const float* a_dst2 = (const float*)d_in[18];
    const float* b2     = (const float*)d_in[19];
    const float* ow     = (const float*)d_in[20];
    const float* ob     = (const float*)d_in[21];

    const int* srcp = ei;
    const int* dstp = ei + NEDGES;
    float* out = (float*)d_out;

    float *ph, *px, *pes, *ped, *pstats;
    int *pdeg, *poff, *ppos, *pcsr;
    cudaGetSymbolAddress((void**)&ph, g_h);
    cudaGetSymbolAddress((void**)&px, g_x);
    cudaGetSymbolAddress((void**)&pes, g_esrc);
    cudaGetSymbolAddress((void**)&ped, g_edst);
    cudaGetSymbolAddress((void**)&pstats, g_stats);
    cudaGetSymbolAddress((void**)&pdeg, g_deg);
    cudaGetSymbolAddress((void**)&poff, g_off);
    cudaGetSymbolAddress((void**)&ppos, g_pos);
    cudaGetSymbolAddress((void**)&pcsr, g_csr);
    float* gsum = pstats;
    float* gsumsq = pstats + 256;
    float* scale = pstats + 512;
    float* shift = pstats + 768;

    const int NODE_BLOCKS = (NNODES + 7) / 8;        // 6250
    const int EDGE_GRID = (NEDGES + 255) / 256;
    const int ROW_TILES = (NNODES + 127) / 128;      // 391
    dim3 gemm_grid0(2, ROW_TILES);                   // M=256
    dim3 gemm_grid2(1, ROW_TILES);                   // M=128

    // ---------- CSR build (once; reused by all 3 layers) ----------
    cudaMemsetAsync(pdeg, 0, NNODES * sizeof(int));
    csr_count<<<EDGE_GRID, 256>>>(dstp, pdeg);
    csr_scan<<<1, 1024>>>(pdeg, poff, ppos);
    csr_fill<<<EDGE_GRID, 256>>>(srcp, dstp, ppos, pcsr);

    // ---------- layer 0: 128 -> 256 (4 heads x 64) ----------
    gemm_tf32<0><<<gemm_grid0, 256>>>(x, W0, ph, NNODES, 128, 256, nullptr, nullptr);
    attn_scores<4, 64><<<NODE_BLOCKS, 256>>>(ph, a_src0, a_dst0, pes, ped);
    cudaMemsetAsync(pstats, 0, 512 * sizeof(float));
    pull_stats<<<NODE_BLOCKS, 256>>>(poff, pcsr, ph, pes, ped, b0, px, gsum, gsumsq);
    norm_prep<<<1, 256>>>(gsum, gsumsq, gnw0, gnb0, gnms0, scale, shift);

    // ---------- layer 1: 256 -> 256 (norm+relu fused into GEMM load) ----------
    gemm_tf32<1><<<gemm_grid0, 256>>>(px, W1, ph, NNODES, 256, 256, scale, shift);
    attn_scores<4, 64><<<NODE_BLOCKS, 256>>>(ph, a_src1, a_dst1, pes, ped);
    cudaMemsetAsync(pstats, 0, 512 * sizeof(float));
    pull_stats<<<NODE_BLOCKS, 256>>>(poff, pcsr, ph, pes, ped, b1, px, gsum, gsumsq);
    norm_prep<<<1, 256>>>(gsum, gsumsq, gnw1, gnb1, gnms1, scale, shift);

    // ---------- layer 2: 256 -> 128 (1 head) + output linear ----------
    gemm_tf32<1><<<gemm_grid2, 256>>>(px, W2, ph, NNODES, 256, 128, scale, shift);
    attn_scores<1, 128><<<NODE_BLOCKS, 256>>>(ph, a_src2, a_dst2, pes, ped);
    pull_out<<<NODE_BLOCKS, 256>>>(poff, pcsr, ph, pes, ped, b2, ow, ob, out);
}

// round 4
// speedup vs baseline: 4.5106x; 1.2038x over previous
#include <cuda_runtime.h>
#include <cstdint>

// ---------------- problem constants ----------------
#define NNODES 50000
#define NEDGES 400000
#define NEG_SLOPE 0.2f
#define EPS 1e-5f

// ---------------- scratch (device globals; no allocs allowed) ----------------
__device__ float g_h  [NNODES * 256];   // post-GEMM hidden
__device__ float g_x  [NNODES * 256];   // activation between layers
__device__ float g_esrc[NNODES * 4];
__device__ float g_edst[NNODES * 4];
__device__ float g_stats[1024];         // [sum(256) | sumsq(256) | scale(256) | shift(256)]
__device__ int   g_deg[NNODES];
__device__ int   g_off[NNODES + 1];
__device__ int   g_pos[NNODES];
__device__ int   g_csr[NEDGES];         // src ids grouped by dst

// ---------------- helpers ----------------------------------------------------
__device__ __forceinline__ uint32_t f2tf32(float x) {
    uint32_t u;
    asm("cvt.rna.tf32.f32 %0, %1;" : "=r"(u) : "f"(x));
    return u;
}

__device__ __forceinline__ void mma_tf32(float& c0, float& c1, float& c2, float& c3,
                                         uint32_t a0, uint32_t a1, uint32_t a2, uint32_t a3,
                                         uint32_t b0, uint32_t b1) {
    asm volatile(
        "mma.sync.aligned.m16n8k8.row.col.f32.tf32.tf32.f32 "
        "{%0,%1,%2,%3}, {%4,%5,%6,%7}, {%8,%9}, {%0,%1,%2,%3};"
        : "+f"(c0), "+f"(c1), "+f"(c2), "+f"(c3)
        : "r"(a0), "r"(a1), "r"(a2), "r"(a3), "r"(b0), "r"(b1));
}

// ---------------- CSR build --------------------------------------------------
__global__ void csr_count(const int* __restrict__ dst, int* __restrict__ deg)
{
    int e = blockIdx.x * blockDim.x + threadIdx.x;
    if (e < NEDGES) atomicAdd(&deg[dst[e]], 1);
}

__global__ void csr_scan(const int* __restrict__ deg, int* __restrict__ off,
                         int* __restrict__ pos)
{
    const int CHUNK = (NNODES + 1023) / 1024;   // 49
    __shared__ int ss[1024];
    int t = threadIdx.x;
    int base = t * CHUNK;
    int s = 0;
    for (int k = 0; k < CHUNK; k++) {
        int i = base + k;
        if (i < NNODES) s += deg[i];
    }
    ss[t] = s;
    __syncthreads();
    for (int o = 1; o < 1024; o <<= 1) {
        int v = (t >= o) ? ss[t - o] : 0;
        __syncthreads();
        ss[t] += v;
        __syncthreads();
    }
    int run = (t > 0) ? ss[t - 1] : 0;
    for (int k = 0; k < CHUNK; k++) {
        int i = base + k;
        if (i < NNODES) {
            off[i] = run;
            pos[i] = run;
            run += deg[i];
        }
    }
    if (t == 1023) off[NNODES] = ss[1023];
}

__global__ void csr_fill(const int* __restrict__ src, const int* __restrict__ dst,
                         int* __restrict__ pos, int* __restrict__ csr)
{
    int e = blockIdx.x * blockDim.x + threadIdx.x;
    if (e < NEDGES) {
        int p = atomicAdd(&pos[dst[e]], 1);
        csr[p] = src[e];
    }
}

// ---------------- tf32 tensor-core GEMM + fused attn-score epilogue ----------
// C[n,m] = sum_k X[n,k]*W[m,k]. BM=128,BN=128,BK=32, 256 thr, warp tile 32x64.
// NORM: per-channel scale/shift + relu applied to X on load.
// HEADS: 4 -> warp tile == one head, direct esrc/edst store.
//        1 -> head spans 2 warps, atomicAdd into zeroed esrc/edst.
//        0 -> no score epilogue.
template <int NORM, int HEADS>
__global__ void gemm_tf32(const float* __restrict__ X, const float* __restrict__ W,
                          float* __restrict__ C, int Nrows, int K, int M,
                          const float* __restrict__ scale, const float* __restrict__ shift,
                          const float* __restrict__ a_srcv, const float* __restrict__ a_dstv,
                          float* __restrict__ esrc, float* __restrict__ edst)
{
    __shared__ float As[128][36];
    __shared__ float Bs[128][36];

    const int tid = threadIdx.x;
    const int rowBase = blockIdx.y * 128;
    const int colBase = blockIdx.x * 128;
    const int warp = tid >> 5;
    const int lane = tid & 31;
    const int wr = (warp & 3) * 32;
    const int wc = (warp >> 2) * 64;
    const int grp = lane >> 2;
    const int tig = lane & 3;

    float c[2][8][4];
#pragma unroll
    for (int t = 0; t < 2; t++)
#pragma unroll
        for (int u = 0; u < 8; u++)
#pragma unroll
            for (int v = 0; v < 4; v++) c[t][u][v] = 0.f;

    for (int k0 = 0; k0 < K; k0 += 32) {
#pragma unroll
        for (int l = 0; l < 4; l++) {
            int idx = tid + l * 256;
            int r = idx >> 3;
            int kk = (idx & 7) * 4;
            int gr = rowBase + r;
            float4 v = make_float4(0.f, 0.f, 0.f, 0.f);
            if (gr < Nrows)
                v = *reinterpret_cast<const float4*>(X + (size_t)gr * K + k0 + kk);
            if (NORM) {
                float4 sc = *reinterpret_cast<const float4*>(scale + k0 + kk);
                float4 sh = *reinterpret_cast<const float4*>(shift + k0 + kk);
                v.x = fmaxf(fmaf(sc.x, v.x, sh.x), 0.f);
                v.y = fmaxf(fmaf(sc.y, v.y, sh.y), 0.f);
                v.z = fmaxf(fmaf(sc.z, v.z, sh.z), 0.f);
                v.w = fmaxf(fmaf(sc.w, v.w, sh.w), 0.f);
            }
            As[r][kk + 0] = __uint_as_float(f2tf32(v.x));
            As[r][kk + 1] = __uint_as_float(f2tf32(v.y));
            As[r][kk + 2] = __uint_as_float(f2tf32(v.z));
            As[r][kk + 3] = __uint_as_float(f2tf32(v.w));
        }
#pragma unroll
        for (int l = 0; l < 4; l++) {
            int idx = tid + l * 256;
            int r = idx >> 3;
            int kk = (idx & 7) * 4;
            float4 v = *reinterpret_cast<const float4*>(W + (size_t)(colBase + r) * K + k0 + kk);
            Bs[r][kk + 0] = __uint_as_float(f2tf32(v.x));
            Bs[r][kk + 1] = __uint_as_float(f2tf32(v.y));
            Bs[r][kk + 2] = __uint_as_float(f2tf32(v.z));
            Bs[r][kk + 3] = __uint_as_float(f2tf32(v.w));
        }
        __syncthreads();

#pragma unroll
        for (int kk = 0; kk < 32; kk += 8) {
            uint32_t a[2][4];
#pragma unroll
            for (int t = 0; t < 2; t++) {
                int r0 = wr + t * 16 + grp;
                a[t][0] = __float_as_uint(As[r0][kk + tig]);
                a[t][1] = __float_as_uint(As[r0 + 8][kk + tig]);
                a[t][2] = __float_as_uint(As[r0][kk + tig + 4]);
                a[t][3] = __float_as_uint(As[r0 + 8][kk + tig + 4]);
            }
            uint32_t b[8][2];
#pragma unroll
            for (int u = 0; u < 8; u++) {
                int cB = wc + u * 8 + grp;
                b[u][0] = __float_as_uint(Bs[cB][kk + tig]);
                b[u][1] = __float_as_uint(Bs[cB][kk + tig + 4]);
            }
#pragma unroll
            for (int t = 0; t < 2; t++)
#pragma unroll
                for (int u = 0; u < 8; u++)
                    mma_tf32(c[t][u][0], c[t][u][1], c[t][u][2], c[t][u][3],
                             a[t][0], a[t][1], a[t][2], a[t][3], b[u][0], b[u][1]);
        }
        __syncthreads();
    }

    // store C
#pragma unroll
    for (int t = 0; t < 2; t++) {
        int gr0 = rowBase + wr + t * 16 + grp;
        int gr1 = gr0 + 8;
#pragma unroll
        for (int u = 0; u < 8; u++) {
            int gc = colBase + wc + u * 8 + tig * 2;
            if (gr0 < Nrows)
                *reinterpret_cast<float2*>(C + (size_t)gr0 * M + gc) =
                    make_float2(c[t][u][0], c[t][u][1]);
            if (gr1 < Nrows)
                *reinterpret_cast<float2*>(C + (size_t)gr1 * M + gc) =
                    make_float2(c[t][u][2], c[t][u][3]);
        }
    }

    // fused attention-score epilogue: per-row dot of h with a_src/a_dst
    if (HEADS > 0) {
        float ss[2][2] = {{0.f, 0.f}, {0.f, 0.f}};
        float sd[2][2] = {{0.f, 0.f}, {0.f, 0.f}};
#pragma unroll
        for (int u = 0; u < 8; u++) {
            int gc = colBase + wc + u * 8 + tig * 2;
            float2 as = *reinterpret_cast<const float2*>(a_srcv + gc);
            float2 ad = *reinterpret_cast<const float2*>(a_dstv + gc);
#pragma unroll
            for (int t = 0; t < 2; t++) {
                ss[t][0] += c[t][u][0] * as.x + c[t][u][1] * as.y;
                ss[t][1] += c[t][u][2] * as.x + c[t][u][3] * as.y;
                sd[t][0] += c[t][u][0] * ad.x + c[t][u][1] * ad.y;
                sd[t][1] += c[t][u][2] * ad.x + c[t][u][3] * ad.y;
            }
        }
#pragma unroll
        for (int o = 1; o <= 2; o <<= 1) {
#pragma unroll
            for (int t = 0; t < 2; t++)
#pragma unroll
                for (int r = 0; r < 2; r++) {
                    ss[t][r] += __shfl_xor_sync(0xffffffffu, ss[t][r], o);
                    sd[t][r] += __shfl_xor_sync(0xffffffffu, sd[t][r], o);
                }
        }
        if (tig == 0) {
            int hw = (colBase + wc) >> ((HEADS == 4) ? 6 : 7);
#pragma unroll
            for (int t = 0; t < 2; t++) {
                int r0 = rowBase + wr + t * 16 + grp;
                int r1 = r0 + 8;
                if (HEADS == 4) {
                    if (r0 < Nrows) { esrc[r0 * 4 + hw] = ss[t][0]; edst[r0 * 4 + hw] = sd[t][0]; }
                    if (r1 < Nrows) { esrc[r1 * 4 + hw] = ss[t][1]; edst[r1 * 4 + hw] = sd[t][1]; }
                } else {
                    if (r0 < Nrows) { atomicAdd(&esrc[r0], ss[t][0]); atomicAdd(&edst[r0], sd[t][0]); }
                    if (r1 < Nrows) { atomicAdd(&esrc[r1], ss[t][1]); atomicAdd(&edst[r1], sd[t][1]); }
                }
            }
        }
    }
}

// ---------------- pull aggregation + softmax-div + bias + fused stats -------
// Warp per destination node. H=4, C=64 (layers 0/1). 8 warps/block = 8 nodes.
__global__ void pull_stats(const int* __restrict__ off, const int* __restrict__ csr,
                           const float* __restrict__ h,
                           const float* __restrict__ esrc, const float* __restrict__ edst,
                           const float* __restrict__ bias, float* __restrict__ xout,
                           float* __restrict__ gsum, float* __restrict__ gsumsq)
{
    const int H = 4, D = 256, PER = 8;
    __shared__ float sm[PER * 256];

    int w = threadIdx.x >> 5;
    int lane = threadIdx.x & 31;
    int n = blockIdx.x * 8 + w;
    const int HH = lane >> 3;

    float v[PER];
#pragma unroll
    for (int i = 0; i < PER; i++) v[i] = 0.f;

    if (n < NNODES) {
        int c0 = lane * PER;
        float ed_l = (lane < H) ? edst[n * H + lane] : 0.f;

        // self loop
        float wl = 0.f;
        if (lane < H) {
            float e = esrc[n * H + lane] + ed_l;
            e = (e > 0.f) ? e : NEG_SLOPE * e;
            wl = __expf(e);
        }
        float myw = __shfl_sync(0xffffffffu, wl, HH);
        float dn = myw;

        float acc[PER];
        {
            const float4* hp = reinterpret_cast<const float4*>(h + (size_t)n * D + c0);
            float4 p = hp[0], q = hp[1];
            acc[0] = myw * p.x; acc[1] = myw * p.y; acc[2] = myw * p.z; acc[3] = myw * p.w;
            acc[4] = myw * q.x; acc[5] = myw * q.y; acc[6] = myw * q.z; acc[7] = myw * q.w;
        }

        int jb = off[n], je = off[n + 1];
        int j = jb;
        for (; j + 1 < je; j += 2) {
            int s0 = csr[j], s1 = csr[j + 1];
            float wl0 = 0.f, wl1 = 0.f;
            if (lane < H) {
                float e0 = esrc[s0 * H + lane] + ed_l;
                float e1 = esrc[s1 * H + lane] + ed_l;
                e0 = (e0 > 0.f) ? e0 : NEG_SLOPE * e0;
                e1 = (e1 > 0.f) ? e1 : NEG_SLOPE * e1;
                wl0 = __expf(e0);
                wl1 = __expf(e1);
            }
            float w0 = __shfl_sync(0xffffffffu, wl0, HH);
            float w1 = __shfl_sync(0xffffffffu, wl1, HH);
            dn += w0 + w1;
            const float4* hp0 = reinterpret_cast<const float4*>(h + (size_t)s0 * D + c0);
            const float4* hp1 = reinterpret_cast<const float4*>(h + (size_t)s1 * D + c0);
            float4 p0 = hp0[0], q0 = hp0[1];
            float4 p1 = hp1[0], q1 = hp1[1];
            acc[0] = fmaf(w0, p0.x, acc[0]); acc[1] = fmaf(w0, p0.y, acc[1]);
            acc[2] = fmaf(w0, p0.z, acc[2]); acc[3] = fmaf(w0, p0.w, acc[3]);
            acc[4] = fmaf(w0, q0.x, acc[4]); acc[5] = fmaf(w0, q0.y, acc[5]);
            acc[6] = fmaf(w0, q0.z, acc[6]); acc[7] = fmaf(w0, q0.w, acc[7]);
            acc[0] = fmaf(w1, p1.x, acc[0]); acc[1] = fmaf(w1, p1.y, acc[1]);
            acc[2] = fmaf(w1, p1.z, acc[2]); acc[3] = fmaf(w1, p1.w, acc[3]);
            acc[4] = fmaf(w1, q1.x, acc[4]); acc[5] = fmaf(w1, q1.y, acc[5]);
            acc[6] = fmaf(w1, q1.z, acc[6]); acc[7] = fmaf(w1, q1.w, acc[7]);
        }
        if (j < je) {
            int s = csr[j];
            float wl2 = 0.f;
            if (lane < H) {
                float e = esrc[s * H + lane] + ed_l;
                e = (e > 0.f) ? e : NEG_SLOPE * e;
                wl2 = __expf(e);
            }
            float w2 = __shfl_sync(0xffffffffu, wl2, HH);
            dn += w2;
            const float4* hp = reinterpret_cast<const float4*>(h + (size_t)s * D + c0);
            float4 p = hp[0], q = hp[1];
            acc[0] = fmaf(w2, p.x, acc[0]); acc[1] = fmaf(w2, p.y, acc[1]);
            acc[2] = fmaf(w2, p.z, acc[2]); acc[3] = fmaf(w2, p.w, acc[3]);
            acc[4] = fmaf(w2, q.x, acc[4]); acc[5] = fmaf(w2, q.y, acc[5]);
            acc[6] = fmaf(w2, q.z, acc[6]); acc[7] = fmaf(w2, q.w, acc[7]);
        }

        float inv = 1.f / (dn + 1e-16f);
#pragma unroll
        for (int i = 0; i < PER; i++) v[i] = fmaf(acc[i], inv, bias[c0 + i]);

        float4 o0 = make_float4(v[0], v[1], v[2], v[3]);
        float4 o1 = make_float4(v[4], v[5], v[6], v[7]);
        float4* xp = reinterpret_cast<float4*>(xout + (size_t)n * D + c0);
        xp[0] = o0; xp[1] = o1;
    }

    // fused per-block stats
#pragma unroll
    for (int i = 0; i < PER; i++) sm[i * 256 + w * 32 + lane] = v[i];
    __syncthreads();

    int c = threadIdx.x;
    int li = c >> 3, ii = c & 7;
    float s = 0.f, s2 = 0.f;
#pragma unroll
    for (int ww = 0; ww < 8; ww++) {
        float x = sm[ii * 256 + ww * 32 + li];
        s += x;
        s2 += x * x;
    }
    atomicAdd(&gsum[c], s);
    atomicAdd(&gsumsq[c], s2);
}

// ---------------- layer-2 pull + output linear ------------------------------
__global__ void pull_out(const int* __restrict__ off, const int* __restrict__ csr,
                         const float* __restrict__ h,
                         const float* __restrict__ esrc, const float* __restrict__ edst,
                         const float* __restrict__ b2, const float* __restrict__ ow,
                         const float* __restrict__ ob, float* __restrict__ out)
{
    const int D = 128, PER = 4;
    int w = threadIdx.x >> 5;
    int lane = threadIdx.x & 31;
    int n = blockIdx.x * 8 + w;
    if (n >= NNODES) return;
    int c0 = lane * PER;

    float ed_l = edst[n];
    float wl = 0.f;
    if (lane == 0) {
        float e = esrc[n] + ed_l;
        e = (e > 0.f) ? e : NEG_SLOPE * e;
        wl = __expf(e);
    }
    float myw = __shfl_sync(0xffffffffu, wl, 0);
    float dn = myw;

    float acc[PER];
    {
        float4 p = *reinterpret_cast<const float4*>(h + (size_t)n * D + c0);
        acc[0] = myw * p.x; acc[1] = myw * p.y; acc[2] = myw * p.z; acc[3] = myw * p.w;
    }

    int jb = off[n], je = off[n + 1];
    int j = jb;
    for (; j + 1 < je; j += 2) {
        int s0 = csr[j], s1 = csr[j + 1];
        float wl0 = 0.f, wl1 = 0.f;
        if (lane == 0) {
            float e0 = esrc[s0] + ed_l;
            float e1 = esrc[s1] + ed_l;
            e0 = (e0 > 0.f) ? e0 : NEG_SLOPE * e0;
            e1 = (e1 > 0.f) ? e1 : NEG_SLOPE * e1;
            wl0 = __expf(e0);
            wl1 = __expf(e1);
        }
        float w0 = __shfl_sync(0xffffffffu, wl0, 0);
        float w1 = __shfl_sync(0xffffffffu, wl1, 0);
        dn += w0 + w1;
        float4 p0 = *reinterpret_cast<const float4*>(h + (size_t)s0 * D + c0);
        float4 p1 = *reinterpret_cast<const float4*>(h + (size_t)s1 * D + c0);
        acc[0] = fmaf(w0, p0.x, acc[0]); acc[1] = fmaf(w0, p0.y, acc[1]);
        acc[2] = fmaf(w0, p0.z, acc[2]); acc[3] = fmaf(w0, p0.w, acc[3]);
        acc[0] = fmaf(w1, p1.x, acc[0]); acc[1] = fmaf(w1, p1.y, acc[1]);
        acc[2] = fmaf(w1, p1.z, acc[2]); acc[3] = fmaf(w1, p1.w, acc[3]);
    }
    if (j < je) {
        int s = csr[j];
        float wl2 = 0.f;
        if (lane == 0) {
            float e = esrc[s] + ed_l;
            e = (e > 0.f) ? e : NEG_SLOPE * e;
            wl2 = __expf(e);
        }
        float w2 = __shfl_sync(0xffffffffu, wl2, 0);
        dn += w2;
        float4 p = *reinterpret_cast<const float4*>(h + (size_t)s * D + c0);
        acc[0] = fmaf(w2, p.x, acc[0]); acc[1] = fmaf(w2, p.y, acc[1]);
        acc[2] = fmaf(w2, p.z, acc[2]); acc[3] = fmaf(w2, p.w, acc[3]);
    }

    float inv = 1.f / (dn + 1e-16f);
    float d0 = 0.f, d1 = 0.f;
#pragma unroll
    for (int i = 0; i < PER; i++) {
        float v = fmaf(acc[i], inv, b2[c0 + i]);
        d0 = fmaf(v, ow[c0 + i], d0);
        d1 = fmaf(v, ow[128 + c0 + i], d1);
    }
#pragma unroll
    for (int o = 16; o > 0; o >>= 1) {
        d0 += __shfl_xor_sync(0xffffffffu, d0, o);
        d1 += __shfl_xor_sync(0xffffffffu, d1, o);
    }
    if (lane == 0) {
        out[n * 2 + 0] = d0 + ob[0];
        out[n * 2 + 1] = d1 + ob[1];
    }
}

// ---------------- norm prep: scale/shift, then zero stats for next layer ----
__global__ void norm_prep(float* __restrict__ gsum, float* __restrict__ gsumsq,
                          const float* __restrict__ gw, const float* __restrict__ gb,
                          const float* __restrict__ ms,
                          float* __restrict__ scale, float* __restrict__ shift)
{
    int c = threadIdx.x;
    const float invN = 1.f / (float)NNODES;
    float mean = gsum[c] * invN;
    float msq = gsumsq[c] * invN;
    float mm = mean * ms[c];
    float var = msq - 2.f * mm * mean + mm * mm;
    float sc = gw[c] * rsqrtf(var + EPS);
    scale[c] = sc;
    shift[c] = gb[c] - sc * mm;
    gsum[c] = 0.f;
    gsumsq[c] = 0.f;
}

// ---------------- launch ----------------------------------------------------
extern "C" void kernel_launch(void* const* d_in, const int* in_sizes, int n_in,
                              void* d_out, int out_size)
{
    const float* x      = (const float*)d_in[0];
    const int*   ei     = (const int*)d_in[1];
    const float* W0     = (const float*)d_in[2];
    const float* a_src0 = (const float*)d_in[3];
    const float* a_dst0 = (const float*)d_in[4];
    const float* b0     = (const float*)d_in[5];
    const float* gnw0   = (const float*)d_in[6];
    const float* gnb0   = (const float*)d_in[7];
    const float* gnms0  = (const float*)d_in[8];
    const float* W1     = (const float*)d_in[9];
    const float* a_src1 = (const float*)d_in[10];
    const float* a_dst1 = (const float*)d_in[11];
    const float* b1     = (const float*)d_in[12];
    const float* gnw1   = (const float*)d_in[13];
    const float* gnb1   = (const float*)d_in[14];
    const float* gnms1  = (const float*)d_in[15];
    const float* W2     = (const float*)d_in[16];
    const float* a_src2 = (const float*)d_in[17];
    const float* a_dst2 = (const float*)d_in[18];
    const float* b2     = (const float*)d_in[19];
    const float* ow     = (const float*)d_in[20];
    const float* ob     = (const float*)d_in[21];

    const int* srcp = ei;
    const int* dstp = ei + NEDGES;
    float* out = (float*)d_out;

    float *ph, *px, *pes, *ped, *pstats;
    int *pdeg, *poff, *ppos, *pcsr;
    cudaGetSymbolAddress((void**)&ph, g_h);
    cudaGetSymbolAddress((void**)&px, g_x);
    cudaGetSymbolAddress((void**)&pes, g_esrc);
    cudaGetSymbolAddress((void**)&ped, g_edst);
    cudaGetSymbolAddress((void**)&pstats, g_stats);
    cudaGetSymbolAddress((void**)&pdeg, g_deg);
    cudaGetSymbolAddress((void**)&poff, g_off);
    cudaGetSymbolAddress((void**)&ppos, g_pos);
    cudaGetSymbolAddress((void**)&pcsr, g_csr);
    float* gsum = pstats;
    float* gsumsq = pstats + 256;
    float* scale = pstats + 512;
    float* shift = pstats + 768;

    const int NODE_BLOCKS = (NNODES + 7) / 8;        // 6250
    const int EDGE_GRID = (NEDGES + 255) / 256;
    const int ROW_TILES = (NNODES + 127) / 128;      // 391
    dim3 gemm_grid0(2, ROW_TILES);                   // M=256
    dim3 gemm_grid2(1, ROW_TILES);                   // M=128

    // ---------- CSR build (once; reused by all 3 layers) ----------
    cudaMemsetAsync(pdeg, 0, NNODES * sizeof(int));
    cudaMemsetAsync(pstats, 0, 512 * sizeof(float));
    csr_count<<<EDGE_GRID, 256>>>(dstp, pdeg);
    csr_scan<<<1, 1024>>>(pdeg, poff, ppos);
    csr_fill<<<EDGE_GRID, 256>>>(srcp, dstp, ppos, pcsr);

    // ---------- layer 0: 128 -> 256 (4 heads x 64), scores fused ----------
    gemm_tf32<0, 4><<<gemm_grid0, 256>>>(x, W0, ph, NNODES, 128, 256,
                                         nullptr, nullptr, a_src0, a_dst0, pes, ped);
    pull_stats<<<NODE_BLOCKS, 256>>>(poff, pcsr, ph, pes, ped, b0, px, gsum, gsumsq);
    norm_prep<<<1, 256>>>(gsum, gsumsq, gnw0, gnb0, gnms0, scale, shift);

    // ---------- layer 1: 256 -> 256 (norm+relu fused into GEMM load) ----------
    gemm_tf32<1, 4><<<gemm_grid0, 256>>>(px, W1, ph, NNODES, 256, 256,
                                         scale, shift, a_src1, a_dst1, pes, ped);
    pull_stats<<<NODE_BLOCKS, 256>>>(poff, pcsr, ph, pes, ped, b1, px, gsum, gsumsq);
    norm_prep<<<1, 256>>>(gsum, gsumsq, gnw1, gnb1, gnms1, scale, shift);

    // ---------- layer 2: 256 -> 128 (1 head) + output linear ----------
    cudaMemsetAsync(pes, 0, NNODES * sizeof(float));
    cudaMemsetAsync(ped, 0, NNODES * sizeof(float));
    gemm_tf32<1, 1><<<gemm_grid2, 256>>>(px, W2, ph, NNODES, 256, 128,
                                         scale, shift, a_src2, a_dst2, pes, ped);
    pull_out<<<NODE_BLOCKS, 256>>>(poff, pcsr, ph, pes, ped, b2, ow, ob, out);
}